// round 14
// baseline (speedup 1.0000x reference)
#include <cuda_runtime.h>
#include <cuda_fp16.h>
#include <cstdint>

// Problem constants
#define NI      100000      // item count
#define NU      131072      // user count
#define NE      64          // embedding size
#define NNZ_S   1500000     // I * TOPK    (divisible by 4)
#define NNZ_U   4194304     // user-item interactions (= 2^22, divisible by 4)

#define BT 256

// Prologue region sizes (R10 structure)
#define UVM_BLOCKS  (NNZ_U / BT)              // one edge per thread
#define RP_TOTAL    ((NI + 1) + (NU + 1))
#define RP_BLOCKS   ((RP_TOTAL + BT - 1) / BT)
#define CV_TOTAL    (NI * NE / 2)             // one half2 per thread
#define CV_BLOCKS   ((CV_TOTAL + BT - 1) / BT)

#define MASK_WORDS  (NNZ_U / 32)

// ---------------------------------------------------------------------------
// Static device scratch (allocation-free rule)
// x stored as half: one row = 64 halves = 8 uint4.
// ---------------------------------------------------------------------------
__device__ uint4    g_xh0[NI * NE / 8];       // 12.8 MB (half storage)
__device__ uint4    g_xh1[NI * NE / 8];       // 12.8 MB
__device__ unsigned g_mask[MASK_WORDS + 1];   // 512 KB keep-bits (+1 pad word)
__device__ int      g_s_rowptr[NI + 1];
__device__ int      g_u_rowptr[NU + 1];

// ---------------------------------------------------------------------------
// threefry2x32 (exact JAX implementation, key = (0, 42))
// ---------------------------------------------------------------------------
__device__ __forceinline__ uint32_t rotl32(uint32_t x, int d) {
    return (x << d) | (x >> (32 - d));
}

__device__ __forceinline__ void threefry2x32(uint32_t k0, uint32_t k1,
                                             uint32_t x0, uint32_t x1,
                                             uint32_t& o0, uint32_t& o1) {
    uint32_t ks2 = k0 ^ k1 ^ 0x1BD11BDAu;
    x0 += k0; x1 += k1;
    x0 += x1; x1 = rotl32(x1, 13); x1 ^= x0;
    x0 += x1; x1 = rotl32(x1, 15); x1 ^= x0;
    x0 += x1; x1 = rotl32(x1, 26); x1 ^= x0;
    x0 += x1; x1 = rotl32(x1,  6); x1 ^= x0;
    x0 += k1; x1 += ks2 + 1u;
    x0 += x1; x1 = rotl32(x1, 17); x1 ^= x0;
    x0 += x1; x1 = rotl32(x1, 29); x1 ^= x0;
    x0 += x1; x1 = rotl32(x1, 16); x1 ^= x0;
    x0 += x1; x1 = rotl32(x1, 24); x1 ^= x0;
    x0 += ks2; x1 += k0 + 2u;
    x0 += x1; x1 = rotl32(x1, 13); x1 ^= x0;
    x0 += x1; x1 = rotl32(x1, 15); x1 ^= x0;
    x0 += x1; x1 = rotl32(x1, 26); x1 ^= x0;
    x0 += x1; x1 = rotl32(x1,  6); x1 ^= x0;
    x0 += k0; x1 += k1 + 3u;
    x0 += x1; x1 = rotl32(x1, 17); x1 ^= x0;
    x0 += x1; x1 = rotl32(x1, 29); x1 ^= x0;
    x0 += x1; x1 = rotl32(x1, 16); x1 ^= x0;
    x0 += x1; x1 = rotl32(x1, 24); x1 ^= x0;
    x0 += k1; x1 += ks2 + 4u;
    x0 += x1; x1 = rotl32(x1, 13); x1 ^= x0;
    x0 += x1; x1 = rotl32(x1, 15); x1 ^= x0;
    x0 += x1; x1 = rotl32(x1, 26); x1 ^= x0;
    x0 += x1; x1 = rotl32(x1,  6); x1 ^= x0;
    x0 += ks2; x1 += k0 + 5u;
    o0 = x0; o1 = x1;
}

// ---------------------------------------------------------------------------
// Fused prologue kernel, 3 regions (VERBATIM R10 structure):
//  A: keep-bit mask (ballot) for JAX-partitionable-threefry dropout
//  B: CSR row-pointer build (S then URM) via lower_bound (+ mask pad word)
//  C: item_emb (fp32) -> half conversion into g_xh0
// ---------------------------------------------------------------------------
__global__ void prologue_kernel(unsigned* __restrict__ mask,
                                const int* __restrict__ s_rows,
                                const int* __restrict__ u_rows,
                                int* __restrict__ s_rowptr,
                                int* __restrict__ u_rowptr,
                                const float* __restrict__ item_emb,
                                __half2* __restrict__ xh) {
    int b = blockIdx.x;
    if (b < UVM_BLOCKS) {
        int i = b * BT + (int)threadIdx.x;       // i < NNZ_U exactly (full warps)
        uint32_t o0, o1;
        threefry2x32(0u, 42u, 0u, (uint32_t)i, o0, o1);
        uint32_t bits = o0 ^ o1;
        float u = __uint_as_float((bits >> 9) | 0x3F800000u) - 1.0f;
        unsigned bal = __ballot_sync(0xFFFFFFFFu, u < 0.8f);
        if ((threadIdx.x & 31) == 0) mask[i >> 5] = bal;
    } else if (b < UVM_BLOCKS + RP_BLOCKS) {
        int t = (b - UVM_BLOCKS) * BT + (int)threadIdx.x;
        if (t == 0) mask[MASK_WORDS] = 0u;       // pad word (value unused)
        if (t <= NI) {
            int lo = 0, hi = NNZ_S;
            while (lo < hi) {
                int mid = (lo + hi) >> 1;
                if (s_rows[mid] < t) lo = mid + 1; else hi = mid;
            }
            s_rowptr[t] = lo;
        }
        int r = t - (NI + 1);
        if (r >= 0 && r <= NU) {
            int lo = 0, hi = NNZ_U;
            while (lo < hi) {
                int mid = (lo + hi) >> 1;
                if (u_rows[mid] < r) lo = mid + 1; else hi = mid;
            }
            u_rowptr[r] = lo;
        }
    } else {
        int t = (b - UVM_BLOCKS - RP_BLOCKS) * BT + (int)threadIdx.x;
        if (t >= CV_TOTAL) return;
        float2 f = *(const float2*)(item_emb + (size_t)t * 2);
        xh[t] = __float22half2_rn(f);
    }
}

// ---------------------------------------------------------------------------
// 8-lane-group-per-row segmented SpMM on half x. Iteration window aligned to
// 4-edge boundaries: one int4 + one float4 load per batch (2 LDG instead of
// 8). Boundary edges are neutralized by zeroing v (select, not branch); any
// v==0 edge skips its gather (uniform across the 8-lane group).
// Software-pipelined: next batch's indices load before current gathers.
// NNZ divisible by 4 => aligned 16B loads never run past the array.
// ---------------------------------------------------------------------------
template <bool WRITE_H, bool WRITE_F>
__global__ void __launch_bounds__(256) spmm_h_kernel(
                            const int*   __restrict__ rowptr,
                            const int*   __restrict__ cols,
                            const float* __restrict__ vals,
                            const uint4* __restrict__ xh,
                            uint4*       __restrict__ yh,
                            float*       __restrict__ yf,
                            int n_rows) {
    int grp = (int)((blockIdx.x * blockDim.x + threadIdx.x) >> 3);  // row id
    int sub = threadIdx.x & 7;                                      // uint4 slot
    if (grp >= n_rows) return;

    int beg = rowptr[grp];
    int end = rowptr[grp + 1];
    int i0  = beg & ~3;                          // aligned window start

    float2 a0 = {0.f, 0.f}, a1 = {0.f, 0.f}, a2 = {0.f, 0.f}, a3 = {0.f, 0.f};

    // Load batch at aligned index b4 (must satisfy b4 < end); zero v for
    // edges outside [beg, end).
    #define LOADB(b4, C, V)                                                    \
    {                                                                          \
        C = __ldg((const int4*)(cols + (b4)));                                 \
        V = __ldg((const float4*)(vals + (b4)));                               \
        if ((b4) < beg || (b4) + 4 > end) {                                    \
            V.x = ((b4)     >= beg && (b4)     < end) ? V.x : 0.f;             \
            V.y = ((b4) + 1 >= beg && (b4) + 1 < end) ? V.y : 0.f;             \
            V.z = ((b4) + 2 >= beg && (b4) + 2 < end) ? V.z : 0.f;             \
            V.w = ((b4) + 3 >= beg && (b4) + 3 < end) ? V.w : 0.f;             \
        }                                                                      \
    }

    int4   c;  float4 v;
    LOADB(i0, c, v)

    for (int i = i0; i < end; i += 4) {
        int4 d = {0, 0, 0, 0}; float4 w = {0.f, 0.f, 0.f, 0.f};
        if (i + 4 < end) LOADB(i + 4, d, w)

        #define ACC_ONE(cc, vv)                                                \
        if ((vv) != 0.f) {                                                     \
            uint4 q = __ldg(xh + (size_t)(cc) * 8 + sub);                      \
            float2 f0 = __half22float2(*(const __half2*)&q.x);                 \
            float2 f1 = __half22float2(*(const __half2*)&q.y);                 \
            float2 f2 = __half22float2(*(const __half2*)&q.z);                 \
            float2 f3 = __half22float2(*(const __half2*)&q.w);                 \
            a0.x = fmaf((vv), f0.x, a0.x); a0.y = fmaf((vv), f0.y, a0.y);      \
            a1.x = fmaf((vv), f1.x, a1.x); a1.y = fmaf((vv), f1.y, a1.y);      \
            a2.x = fmaf((vv), f2.x, a2.x); a2.y = fmaf((vv), f2.y, a2.y);      \
            a3.x = fmaf((vv), f3.x, a3.x); a3.y = fmaf((vv), f3.y, a3.y);      \
        }
        ACC_ONE(c.x, v.x)
        ACC_ONE(c.y, v.y)
        ACC_ONE(c.z, v.z)
        ACC_ONE(c.w, v.w)
        #undef ACC_ONE

        c = d; v = w;
    }
    #undef LOADB

    if (WRITE_H) {
        __half2 h0 = __float22half2_rn(a0);
        __half2 h1 = __float22half2_rn(a1);
        __half2 h2 = __float22half2_rn(a2);
        __half2 h3 = __float22half2_rn(a3);
        uint4 q;
        q.x = *(const uint32_t*)&h0;
        q.y = *(const uint32_t*)&h1;
        q.z = *(const uint32_t*)&h2;
        q.w = *(const uint32_t*)&h3;
        yh[(size_t)grp * 8 + sub] = q;
    }
    if (WRITE_F) {
        float4 f0 = make_float4(a0.x, a0.y, a1.x, a1.y);
        float4 f1 = make_float4(a2.x, a2.y, a3.x, a3.y);
        *(float4*)(yf + (size_t)grp * NE + sub * 8)     = f0;
        *(float4*)(yf + (size_t)grp * NE + sub * 8 + 4) = f1;
    }
}

// ---------------------------------------------------------------------------
// U-spmm: aligned int4 col loads (unconditional — breaks the bits->col-load
// chain) + keep-bits from the bitmask via funnelshift; boundary edges are
// cleared in the bits. Kept edges accumulate unscaled; exact 1.25 at the end.
// ---------------------------------------------------------------------------
__global__ void __launch_bounds__(256) spmm_u_kernel(
                            const int*      __restrict__ rowptr,
                            const int*      __restrict__ cols,
                            const unsigned* __restrict__ mask,
                            const uint4*    __restrict__ xh,
                            float*          __restrict__ yf,
                            int n_rows) {
    int grp = (int)((blockIdx.x * blockDim.x + threadIdx.x) >> 3);  // row id
    int sub = threadIdx.x & 7;                                      // uint4 slot
    if (grp >= n_rows) return;

    int beg = rowptr[grp];
    int end = rowptr[grp + 1];
    int i0  = beg & ~3;

    float2 a0 = {0.f, 0.f}, a1 = {0.f, 0.f}, a2 = {0.f, 0.f}, a3 = {0.f, 0.f};

    // Load batch at aligned b4 (< end): 4 cols + 4 keep-bits, boundary-masked.
    #define LOADB(b4, C, BITS)                                                 \
    {                                                                          \
        C = __ldg((const int4*)(cols + (b4)));                                 \
        unsigned wd = (unsigned)(b4) >> 5;                                     \
        unsigned sh = (unsigned)(b4) & 31u;                                    \
        unsigned m0 = __ldg(mask + wd);                                        \
        unsigned m1 = __ldg(mask + wd + 1);                                    \
        BITS = __funnelshift_r(m0, m1, sh) & 0xFu;                             \
        if ((b4) < beg)        BITS &= 0xFu << (beg - (b4));                   \
        if ((b4) + 4 > end)    BITS &= (1u << (end - (b4))) - 1u;              \
    }

    int4 c; unsigned bits = 0u;
    LOADB(i0, c, bits)

    for (int i = i0; i < end; i += 4) {
        int4 d = {0, 0, 0, 0}; unsigned nbits = 0u;
        if (i + 4 < end) LOADB(i + 4, d, nbits)

        #define ACC_ONE(cc, K)                                                 \
        if (bits & (K)) {                                                      \
            uint4 q = __ldg(xh + (size_t)(cc) * 8 + sub);                      \
            float2 f0 = __half22float2(*(const __half2*)&q.x);                 \
            float2 f1 = __half22float2(*(const __half2*)&q.y);                 \
            float2 f2 = __half22float2(*(const __half2*)&q.z);                 \
            float2 f3 = __half22float2(*(const __half2*)&q.w);                 \
            a0.x += f0.x; a0.y += f0.y;                                        \
            a1.x += f1.x; a1.y += f1.y;                                        \
            a2.x += f2.x; a2.y += f2.y;                                        \
            a3.x += f3.x; a3.y += f3.y;                                        \
        }
        ACC_ONE(c.x, 1u)
        ACC_ONE(c.y, 2u)
        ACC_ONE(c.z, 4u)
        ACC_ONE(c.w, 8u)
        #undef ACC_ONE

        bits = nbits; c = d;
    }
    #undef LOADB

    const float s = 1.25f;   // 1/keep, exact
    float4 f0 = make_float4(s * a0.x, s * a0.y, s * a1.x, s * a1.y);
    float4 f1 = make_float4(s * a2.x, s * a2.y, s * a3.x, s * a3.y);
    *(float4*)(yf + (size_t)grp * NE + sub * 8)     = f0;
    *(float4*)(yf + (size_t)grp * NE + sub * 8 + 4) = f1;
}

// ---------------------------------------------------------------------------
// Launch
// ---------------------------------------------------------------------------
extern "C" void kernel_launch(void* const* d_in, const int* in_sizes, int n_in,
                              void* d_out, int out_size) {
    // Classify inputs by element count (robust to metadata ordering).
    const float* item_emb = nullptr;
    const void*  s_trip[3] = {nullptr, nullptr, nullptr};   // vals, rows, cols
    const void*  u_trip[3] = {nullptr, nullptr, nullptr};   // vals, rows, cols
    int si = 0, ui = 0;
    for (int k = 0; k < n_in; k++) {
        if (in_sizes[k] == NI * NE)      item_emb = (const float*)d_in[k];
        else if (in_sizes[k] == NNZ_S)   { if (si < 3) s_trip[si++] = d_in[k]; }
        else if (in_sizes[k] == NNZ_U)   { if (ui < 3) u_trip[ui++] = d_in[k]; }
    }
    const float* S_vals   = (const float*)s_trip[0];
    const int*   S_rows   = (const int*)  s_trip[1];
    const int*   S_cols   = (const int*)  s_trip[2];
    const int*   urm_rows = (const int*)  u_trip[1];
    const int*   urm_cols = (const int*)  u_trip[2];

    float* out_user = (float*)d_out;                       // [NU, NE]
    float* out_x    = (float*)d_out + (size_t)NU * NE;     // [NI, NE]

    // Resolve device-global scratch addresses (host side).
    uint4 *xh0, *xh1;
    unsigned *mask;
    int *s_rowptr, *u_rowptr;
    cudaGetSymbolAddress((void**)&xh0,      g_xh0);
    cudaGetSymbolAddress((void**)&xh1,      g_xh1);
    cudaGetSymbolAddress((void**)&mask,     g_mask);
    cudaGetSymbolAddress((void**)&s_rowptr, g_s_rowptr);
    cudaGetSymbolAddress((void**)&u_rowptr, g_u_rowptr);

    // Fused prologue: dropout mask + rowptrs + item_emb->half, one launch
    prologue_kernel<<<UVM_BLOCKS + RP_BLOCKS + CV_BLOCKS, BT>>>(
        mask, S_rows, urm_rows, s_rowptr, u_rowptr, item_emb, (__half2*)xh0);

    // 3-hop item-graph convolution (8-lane group per row: 32 rows / block)
    const int RPB = BT / 8;
    dim3 gridS((NI + RPB - 1) / RPB);
    spmm_h_kernel<true, false><<<gridS, BT>>>(
        s_rowptr, S_cols, S_vals, xh0, xh1, nullptr, NI);
    spmm_h_kernel<true, false><<<gridS, BT>>>(
        s_rowptr, S_cols, S_vals, xh1, xh0, nullptr, NI);
    spmm_h_kernel<true, true><<<gridS, BT>>>(
        s_rowptr, S_cols, S_vals, xh0, xh1, out_x, NI);

    // user_emb = (dropout(URM)) @ x — bitmask dropout, half gathers
    dim3 gridU((NU + RPB - 1) / RPB);
    spmm_u_kernel<<<gridU, BT>>>(u_rowptr, urm_cols, mask, xh1, out_user, NU);
}

// round 15
// speedup vs baseline: 1.0627x; 1.0627x over previous
#include <cuda_runtime.h>
#include <cuda_fp16.h>
#include <cstdint>

// Problem constants
#define NI      100000      // item count
#define NU      131072      // user count
#define NE      64          // embedding size
#define NNZ_S   1500000     // I * TOPK
#define NNZ_U   4194304     // user-item interactions (= 2^22)

#define BT 256

// Prologue region sizes (R10 structure)
#define UVM_BLOCKS  (NNZ_U / BT)              // one edge per thread
#define RP_TOTAL    ((NI + 1) + (NU + 1))
#define RP_BLOCKS   ((RP_TOTAL + BT - 1) / BT)
#define CV_TOTAL    (NI * NE / 2)             // one half2 per thread
#define CV_BLOCKS   ((CV_TOTAL + BT - 1) / BT)

#define MASK_WORDS  (NNZ_U / 32)

// ---------------------------------------------------------------------------
// Static device scratch (allocation-free rule)
// x stored as half: one row = 64 halves = 8 uint4.
// ---------------------------------------------------------------------------
__device__ uint4    g_xh0[NI * NE / 8];       // 12.8 MB (half storage)
__device__ uint4    g_xh1[NI * NE / 8];       // 12.8 MB
__device__ unsigned g_mask[MASK_WORDS + 1];   // 512 KB keep-bits (+1 pad word)
__device__ int      g_s_rowptr[NI + 1];
__device__ int      g_u_rowptr[NU + 1];
__device__ int      g_ucols[NNZ_U];           // 16.8 MB compacted kept cols
__device__ int      g_ucnt[NU];               // kept-edge count per user row

// ---------------------------------------------------------------------------
// threefry2x32 (exact JAX implementation, key = (0, 42))
// ---------------------------------------------------------------------------
__device__ __forceinline__ uint32_t rotl32(uint32_t x, int d) {
    return (x << d) | (x >> (32 - d));
}

__device__ __forceinline__ void threefry2x32(uint32_t k0, uint32_t k1,
                                             uint32_t x0, uint32_t x1,
                                             uint32_t& o0, uint32_t& o1) {
    uint32_t ks2 = k0 ^ k1 ^ 0x1BD11BDAu;
    x0 += k0; x1 += k1;
    x0 += x1; x1 = rotl32(x1, 13); x1 ^= x0;
    x0 += x1; x1 = rotl32(x1, 15); x1 ^= x0;
    x0 += x1; x1 = rotl32(x1, 26); x1 ^= x0;
    x0 += x1; x1 = rotl32(x1,  6); x1 ^= x0;
    x0 += k1; x1 += ks2 + 1u;
    x0 += x1; x1 = rotl32(x1, 17); x1 ^= x0;
    x0 += x1; x1 = rotl32(x1, 29); x1 ^= x0;
    x0 += x1; x1 = rotl32(x1, 16); x1 ^= x0;
    x0 += x1; x1 = rotl32(x1, 24); x1 ^= x0;
    x0 += ks2; x1 += k0 + 2u;
    x0 += x1; x1 = rotl32(x1, 13); x1 ^= x0;
    x0 += x1; x1 = rotl32(x1, 15); x1 ^= x0;
    x0 += x1; x1 = rotl32(x1, 26); x1 ^= x0;
    x0 += x1; x1 = rotl32(x1,  6); x1 ^= x0;
    x0 += k0; x1 += k1 + 3u;
    x0 += x1; x1 = rotl32(x1, 17); x1 ^= x0;
    x0 += x1; x1 = rotl32(x1, 29); x1 ^= x0;
    x0 += x1; x1 = rotl32(x1, 16); x1 ^= x0;
    x0 += x1; x1 = rotl32(x1, 24); x1 ^= x0;
    x0 += k1; x1 += ks2 + 4u;
    x0 += x1; x1 = rotl32(x1, 13); x1 ^= x0;
    x0 += x1; x1 = rotl32(x1, 15); x1 ^= x0;
    x0 += x1; x1 = rotl32(x1, 26); x1 ^= x0;
    x0 += x1; x1 = rotl32(x1,  6); x1 ^= x0;
    x0 += ks2; x1 += k0 + 5u;
    o0 = x0; o1 = x1;
}

// ---------------------------------------------------------------------------
// Fused prologue kernel, 3 regions (VERBATIM R10 structure):
//  A: keep-bit mask (ballot) for JAX-partitionable-threefry dropout
//  B: CSR row-pointer build (S then URM) via lower_bound (+ mask pad word)
//  C: item_emb (fp32) -> half conversion into g_xh0
// ---------------------------------------------------------------------------
__global__ void prologue_kernel(unsigned* __restrict__ mask,
                                const int* __restrict__ s_rows,
                                const int* __restrict__ u_rows,
                                int* __restrict__ s_rowptr,
                                int* __restrict__ u_rowptr,
                                const float* __restrict__ item_emb,
                                __half2* __restrict__ xh) {
    int b = blockIdx.x;
    if (b < UVM_BLOCKS) {
        int i = b * BT + (int)threadIdx.x;       // i < NNZ_U exactly (full warps)
        uint32_t o0, o1;
        threefry2x32(0u, 42u, 0u, (uint32_t)i, o0, o1);
        uint32_t bits = o0 ^ o1;
        float u = __uint_as_float((bits >> 9) | 0x3F800000u) - 1.0f;
        unsigned bal = __ballot_sync(0xFFFFFFFFu, u < 0.8f);
        if ((threadIdx.x & 31) == 0) mask[i >> 5] = bal;
    } else if (b < UVM_BLOCKS + RP_BLOCKS) {
        int t = (b - UVM_BLOCKS) * BT + (int)threadIdx.x;
        if (t == 0) mask[MASK_WORDS] = 0u;       // pad word (value unused)
        if (t <= NI) {
            int lo = 0, hi = NNZ_S;
            while (lo < hi) {
                int mid = (lo + hi) >> 1;
                if (s_rows[mid] < t) lo = mid + 1; else hi = mid;
            }
            s_rowptr[t] = lo;
        }
        int r = t - (NI + 1);
        if (r >= 0 && r <= NU) {
            int lo = 0, hi = NNZ_U;
            while (lo < hi) {
                int mid = (lo + hi) >> 1;
                if (u_rows[mid] < r) lo = mid + 1; else hi = mid;
            }
            u_rowptr[r] = lo;
        }
    } else {
        int t = (b - UVM_BLOCKS - RP_BLOCKS) * BT + (int)threadIdx.x;
        if (t >= CV_TOTAL) return;
        float2 f = *(const float2*)(item_emb + (size_t)t * 2);
        xh[t] = __float22half2_rn(f);
    }
}

// ---------------------------------------------------------------------------
// Edge compaction: warp per user row. Kept cols are written densely at the
// row's own base offset (order-preserving ballot-prefix), count in ucnt.
// ---------------------------------------------------------------------------
__global__ void __launch_bounds__(256) compact_kernel(
                                const int*      __restrict__ u_rowptr,
                                const int*      __restrict__ urm_cols,
                                const unsigned* __restrict__ mask,
                                int*            __restrict__ ucols,
                                int*            __restrict__ ucnt) {
    int r = (int)blockIdx.x * (BT / 32) + (int)(threadIdx.x >> 5);
    if (r >= NU) return;
    int lane = (int)(threadIdx.x & 31);

    int beg = u_rowptr[r];
    int end = u_rowptr[r + 1];
    int out = beg;

    for (int i0 = beg; i0 < end; i0 += 32) {
        int i = i0 + lane;
        bool active = (i < end);
        bool keep = false;
        if (active) keep = (__ldg(mask + (i >> 5)) >> (i & 31)) & 1u;
        unsigned bal = __ballot_sync(0xFFFFFFFFu, keep);
        if (keep) {
            int pre = __popc(bal & ((1u << lane) - 1u));
            ucols[out + pre] = __ldg(urm_cols + i);
        }
        out += __popc(bal);
    }
    if (lane == 0) ucnt[r] = out - beg;
}

// ---------------------------------------------------------------------------
// 8-lane-group-per-row segmented SpMM on half x (VERBATIM R10) with
// software-pipelined cols/vals.
// ---------------------------------------------------------------------------
template <bool WRITE_H, bool WRITE_F>
__global__ void __launch_bounds__(256) spmm_h_kernel(
                            const int*   __restrict__ rowptr,
                            const int*   __restrict__ cols,
                            const float* __restrict__ vals,
                            const uint4* __restrict__ xh,
                            uint4*       __restrict__ yh,
                            float*       __restrict__ yf,
                            int n_rows) {
    int grp = (int)((blockIdx.x * blockDim.x + threadIdx.x) >> 3);  // row id
    int sub = threadIdx.x & 7;                                      // uint4 slot
    if (grp >= n_rows) return;

    int beg = rowptr[grp];
    int end = rowptr[grp + 1];

    float2 a0 = {0.f, 0.f}, a1 = {0.f, 0.f}, a2 = {0.f, 0.f}, a3 = {0.f, 0.f};

    // Preload first index batch
    int   c0 = 0, c1 = 0, c2 = 0, c3 = 0;
    float v0 = 0.f, v1 = 0.f, v2 = 0.f, v3 = 0.f;
    if (beg     < end) { c0 = __ldg(cols + beg);     v0 = __ldg(vals + beg);     }
    if (beg + 1 < end) { c1 = __ldg(cols + beg + 1); v1 = __ldg(vals + beg + 1); }
    if (beg + 2 < end) { c2 = __ldg(cols + beg + 2); v2 = __ldg(vals + beg + 2); }
    if (beg + 3 < end) { c3 = __ldg(cols + beg + 3); v3 = __ldg(vals + beg + 3); }

    for (int i = beg; i < end; i += 4) {
        // Prefetch next index batch (independent of current gathers)
        int n = i + 4;
        int   d0 = 0, d1 = 0, d2 = 0, d3 = 0;
        float w0 = 0.f, w1 = 0.f, w2 = 0.f, w3 = 0.f;
        if (n     < end) { d0 = __ldg(cols + n);     w0 = __ldg(vals + n);     }
        if (n + 1 < end) { d1 = __ldg(cols + n + 1); w1 = __ldg(vals + n + 1); }
        if (n + 2 < end) { d2 = __ldg(cols + n + 2); w2 = __ldg(vals + n + 2); }
        if (n + 3 < end) { d3 = __ldg(cols + n + 3); w3 = __ldg(vals + n + 3); }

        #define ACC_ONE(c, v)                                                  \
        {                                                                      \
            uint4 q = __ldg(xh + (size_t)(c) * 8 + sub);                       \
            float2 f0 = __half22float2(*(const __half2*)&q.x);                 \
            float2 f1 = __half22float2(*(const __half2*)&q.y);                 \
            float2 f2 = __half22float2(*(const __half2*)&q.z);                 \
            float2 f3 = __half22float2(*(const __half2*)&q.w);                 \
            a0.x = fmaf((v), f0.x, a0.x); a0.y = fmaf((v), f0.y, a0.y);        \
            a1.x = fmaf((v), f1.x, a1.x); a1.y = fmaf((v), f1.y, a1.y);        \
            a2.x = fmaf((v), f2.x, a2.x); a2.y = fmaf((v), f2.y, a2.y);        \
            a3.x = fmaf((v), f3.x, a3.x); a3.y = fmaf((v), f3.y, a3.y);        \
        }
        ACC_ONE(c0, v0)
        ACC_ONE(c1, v1)
        ACC_ONE(c2, v2)
        ACC_ONE(c3, v3)
        #undef ACC_ONE

        c0 = d0; c1 = d1; c2 = d2; c3 = d3;
        v0 = w0; v1 = w1; v2 = w2; v3 = w3;
    }

    if (WRITE_H) {
        __half2 h0 = __float22half2_rn(a0);
        __half2 h1 = __float22half2_rn(a1);
        __half2 h2 = __float22half2_rn(a2);
        __half2 h3 = __float22half2_rn(a3);
        uint4 q;
        q.x = *(const uint32_t*)&h0;
        q.y = *(const uint32_t*)&h1;
        q.z = *(const uint32_t*)&h2;
        q.w = *(const uint32_t*)&h3;
        yh[(size_t)grp * 8 + sub] = q;
    }
    if (WRITE_F) {
        float4 f0 = make_float4(a0.x, a0.y, a1.x, a1.y);
        float4 f1 = make_float4(a2.x, a2.y, a3.x, a3.y);
        *(float4*)(yf + (size_t)grp * NE + sub * 8)     = f0;
        *(float4*)(yf + (size_t)grp * NE + sub * 8 + 4) = f1;
    }
}

// ---------------------------------------------------------------------------
// U-spmm on COMPACTED kept-edge lists: R10 loop shape, no mask, no vals —
// every edge contributes x[col]; exact 1.25 scale at the end.
// ---------------------------------------------------------------------------
__global__ void __launch_bounds__(256) spmm_u_kernel(
                            const int*   __restrict__ rowptr,
                            const int*   __restrict__ ucnt,
                            const int*   __restrict__ ucols,
                            const uint4* __restrict__ xh,
                            float*       __restrict__ yf,
                            int n_rows) {
    int grp = (int)((blockIdx.x * blockDim.x + threadIdx.x) >> 3);  // row id
    int sub = threadIdx.x & 7;                                      // uint4 slot
    if (grp >= n_rows) return;

    int beg = rowptr[grp];
    int end = beg + ucnt[grp];

    float2 a0 = {0.f, 0.f}, a1 = {0.f, 0.f}, a2 = {0.f, 0.f}, a3 = {0.f, 0.f};

    // Preload first index batch (validity in k flags)
    int  c0 = 0, c1 = 0, c2 = 0, c3 = 0;
    bool k0 = false, k1 = false, k2 = false, k3 = false;
    if (beg     < end) { c0 = __ldg(ucols + beg);     k0 = true; }
    if (beg + 1 < end) { c1 = __ldg(ucols + beg + 1); k1 = true; }
    if (beg + 2 < end) { c2 = __ldg(ucols + beg + 2); k2 = true; }
    if (beg + 3 < end) { c3 = __ldg(ucols + beg + 3); k3 = true; }

    for (int i = beg; i < end; i += 4) {
        int n = i + 4;
        int  d0 = 0, d1 = 0, d2 = 0, d3 = 0;
        bool m0 = false, m1 = false, m2 = false, m3 = false;
        if (n     < end) { d0 = __ldg(ucols + n);     m0 = true; }
        if (n + 1 < end) { d1 = __ldg(ucols + n + 1); m1 = true; }
        if (n + 2 < end) { d2 = __ldg(ucols + n + 2); m2 = true; }
        if (n + 3 < end) { d3 = __ldg(ucols + n + 3); m3 = true; }

        #define ACC_ONE(c, k)                                                  \
        if (k) {                                                               \
            uint4 q = __ldg(xh + (size_t)(c) * 8 + sub);                       \
            float2 f0 = __half22float2(*(const __half2*)&q.x);                 \
            float2 f1 = __half22float2(*(const __half2*)&q.y);                 \
            float2 f2 = __half22float2(*(const __half2*)&q.z);                 \
            float2 f3 = __half22float2(*(const __half2*)&q.w);                 \
            a0.x += f0.x; a0.y += f0.y;                                        \
            a1.x += f1.x; a1.y += f1.y;                                        \
            a2.x += f2.x; a2.y += f2.y;                                        \
            a3.x += f3.x; a3.y += f3.y;                                        \
        }
        ACC_ONE(c0, k0)
        ACC_ONE(c1, k1)
        ACC_ONE(c2, k2)
        ACC_ONE(c3, k3)
        #undef ACC_ONE

        c0 = d0; c1 = d1; c2 = d2; c3 = d3;
        k0 = m0; k1 = m1; k2 = m2; k3 = m3;
    }

    const float s = 1.25f;   // 1/keep, exact
    float4 f0 = make_float4(s * a0.x, s * a0.y, s * a1.x, s * a1.y);
    float4 f1 = make_float4(s * a2.x, s * a2.y, s * a3.x, s * a3.y);
    *(float4*)(yf + (size_t)grp * NE + sub * 8)     = f0;
    *(float4*)(yf + (size_t)grp * NE + sub * 8 + 4) = f1;
}

// ---------------------------------------------------------------------------
// Launch
// ---------------------------------------------------------------------------
extern "C" void kernel_launch(void* const* d_in, const int* in_sizes, int n_in,
                              void* d_out, int out_size) {
    // Classify inputs by element count (robust to metadata ordering).
    const float* item_emb = nullptr;
    const void*  s_trip[3] = {nullptr, nullptr, nullptr};   // vals, rows, cols
    const void*  u_trip[3] = {nullptr, nullptr, nullptr};   // vals, rows, cols
    int si = 0, ui = 0;
    for (int k = 0; k < n_in; k++) {
        if (in_sizes[k] == NI * NE)      item_emb = (const float*)d_in[k];
        else if (in_sizes[k] == NNZ_S)   { if (si < 3) s_trip[si++] = d_in[k]; }
        else if (in_sizes[k] == NNZ_U)   { if (ui < 3) u_trip[ui++] = d_in[k]; }
    }
    const float* S_vals   = (const float*)s_trip[0];
    const int*   S_rows   = (const int*)  s_trip[1];
    const int*   S_cols   = (const int*)  s_trip[2];
    const int*   urm_rows = (const int*)  u_trip[1];
    const int*   urm_cols = (const int*)  u_trip[2];

    float* out_user = (float*)d_out;                       // [NU, NE]
    float* out_x    = (float*)d_out + (size_t)NU * NE;     // [NI, NE]

    // Resolve device-global scratch addresses (host side).
    uint4 *xh0, *xh1;
    unsigned *mask;
    int *s_rowptr, *u_rowptr, *ucols, *ucnt;
    cudaGetSymbolAddress((void**)&xh0,      g_xh0);
    cudaGetSymbolAddress((void**)&xh1,      g_xh1);
    cudaGetSymbolAddress((void**)&mask,     g_mask);
    cudaGetSymbolAddress((void**)&s_rowptr, g_s_rowptr);
    cudaGetSymbolAddress((void**)&u_rowptr, g_u_rowptr);
    cudaGetSymbolAddress((void**)&ucols,    g_ucols);
    cudaGetSymbolAddress((void**)&ucnt,     g_ucnt);

    // Fused prologue: dropout mask + rowptrs + item_emb->half, one launch
    prologue_kernel<<<UVM_BLOCKS + RP_BLOCKS + CV_BLOCKS, BT>>>(
        mask, S_rows, urm_rows, s_rowptr, u_rowptr, item_emb, (__half2*)xh0);

    // Compact kept URM edges (warp per row)
    compact_kernel<<<(NU + (BT / 32) - 1) / (BT / 32), BT>>>(
        u_rowptr, urm_cols, mask, ucols, ucnt);

    // 3-hop item-graph convolution (8-lane group per row: 32 rows / block)
    const int RPB = BT / 8;
    dim3 gridS((NI + RPB - 1) / RPB);
    spmm_h_kernel<true, false><<<gridS, BT>>>(
        s_rowptr, S_cols, S_vals, xh0, xh1, nullptr, NI);
    spmm_h_kernel<true, false><<<gridS, BT>>>(
        s_rowptr, S_cols, S_vals, xh1, xh0, nullptr, NI);
    spmm_h_kernel<true, true><<<gridS, BT>>>(
        s_rowptr, S_cols, S_vals, xh0, xh1, out_x, NI);

    // user_emb = URM-kept @ x — compacted edge lists, half gathers
    dim3 gridU((NU + RPB - 1) / RPB);
    spmm_u_kernel<<<gridU, BT>>>(u_rowptr, ucnt, ucols, xh1, out_user, NU);
}

// round 16
// speedup vs baseline: 1.1403x; 1.0730x over previous
#include <cuda_runtime.h>
#include <cuda_fp16.h>
#include <cstdint>

// Problem constants
#define NI      100000      // item count
#define NU      131072      // user count
#define NE      64          // embedding size
#define NNZ_S   1500000     // I * TOPK
#define NNZ_U   4194304     // user-item interactions (= 2^22)

#define BT 256

// Region sizes
#define UVM_BLOCKS  (NNZ_U / BT)              // one edge per thread
#define RP_TOTAL    ((NI + 1) + (NU + 1))
#define RP_BLOCKS   ((RP_TOTAL + BT - 1) / BT)
#define CV_TOTAL    (NI * NE / 2)             // one half2 per thread
#define CV_BLOCKS   ((CV_TOTAL + BT - 1) / BT)

#define MASK_WORDS  (NNZ_U / 32)

// ---------------------------------------------------------------------------
// Static device scratch (allocation-free rule)
// x stored as half: one row = 64 halves = 8 uint4.
// ---------------------------------------------------------------------------
__device__ uint4    g_xh0[NI * NE / 8];       // 12.8 MB (half storage)
__device__ uint4    g_xh1[NI * NE / 8];       // 12.8 MB
__device__ unsigned g_mask[MASK_WORDS + 1];   // 512 KB keep-bits (+1 pad word)
__device__ int      g_s_rowptr[NI + 1];
__device__ int      g_u_rowptr[NU + 1];

// ---------------------------------------------------------------------------
// threefry2x32 (exact JAX implementation, key = (0, 42))
// ---------------------------------------------------------------------------
__device__ __forceinline__ uint32_t rotl32(uint32_t x, int d) {
    return (x << d) | (x >> (32 - d));
}

__device__ __forceinline__ void threefry2x32(uint32_t k0, uint32_t k1,
                                             uint32_t x0, uint32_t x1,
                                             uint32_t& o0, uint32_t& o1) {
    uint32_t ks2 = k0 ^ k1 ^ 0x1BD11BDAu;
    x0 += k0; x1 += k1;
    x0 += x1; x1 = rotl32(x1, 13); x1 ^= x0;
    x0 += x1; x1 = rotl32(x1, 15); x1 ^= x0;
    x0 += x1; x1 = rotl32(x1, 26); x1 ^= x0;
    x0 += x1; x1 = rotl32(x1,  6); x1 ^= x0;
    x0 += k1; x1 += ks2 + 1u;
    x0 += x1; x1 = rotl32(x1, 17); x1 ^= x0;
    x0 += x1; x1 = rotl32(x1, 29); x1 ^= x0;
    x0 += x1; x1 = rotl32(x1, 16); x1 ^= x0;
    x0 += x1; x1 = rotl32(x1, 24); x1 ^= x0;
    x0 += ks2; x1 += k0 + 2u;
    x0 += x1; x1 = rotl32(x1, 13); x1 ^= x0;
    x0 += x1; x1 = rotl32(x1, 15); x1 ^= x0;
    x0 += x1; x1 = rotl32(x1, 26); x1 ^= x0;
    x0 += x1; x1 = rotl32(x1,  6); x1 ^= x0;
    x0 += k0; x1 += k1 + 3u;
    x0 += x1; x1 = rotl32(x1, 17); x1 ^= x0;
    x0 += x1; x1 = rotl32(x1, 29); x1 ^= x0;
    x0 += x1; x1 = rotl32(x1, 16); x1 ^= x0;
    x0 += x1; x1 = rotl32(x1, 24); x1 ^= x0;
    x0 += k1; x1 += ks2 + 4u;
    x0 += x1; x1 = rotl32(x1, 13); x1 ^= x0;
    x0 += x1; x1 = rotl32(x1, 15); x1 ^= x0;
    x0 += x1; x1 = rotl32(x1, 26); x1 ^= x0;
    x0 += x1; x1 = rotl32(x1,  6); x1 ^= x0;
    x0 += ks2; x1 += k0 + 5u;
    o0 = x0; o1 = x1;
}

// ---------------------------------------------------------------------------
// Mask kernel (prologue region A split out — runs on a forked stream,
// concurrent with the L2-latency-bound hops):
// keep-bit mask (ballot) for JAX-partitionable-threefry bernoulli dropout.
// ---------------------------------------------------------------------------
__global__ void mask_kernel(unsigned* __restrict__ mask) {
    int i = (int)blockIdx.x * BT + (int)threadIdx.x;  // i < NNZ_U (full warps)
    uint32_t o0, o1;
    threefry2x32(0u, 42u, 0u, (uint32_t)i, o0, o1);
    uint32_t bits = o0 ^ o1;
    float u = __uint_as_float((bits >> 9) | 0x3F800000u) - 1.0f;
    unsigned bal = __ballot_sync(0xFFFFFFFFu, u < 0.8f);
    if ((threadIdx.x & 31) == 0) mask[i >> 5] = bal;
}

// ---------------------------------------------------------------------------
// Prologue (regions B + C of the R10 prologue):
//  B: CSR row-pointer build (S then URM) via lower_bound (+ mask pad word)
//  C: item_emb (fp32) -> half conversion into g_xh0
// ---------------------------------------------------------------------------
__global__ void prologue_kernel(unsigned* __restrict__ mask,
                                const int* __restrict__ s_rows,
                                const int* __restrict__ u_rows,
                                int* __restrict__ s_rowptr,
                                int* __restrict__ u_rowptr,
                                const float* __restrict__ item_emb,
                                __half2* __restrict__ xh) {
    int b = blockIdx.x;
    if (b < RP_BLOCKS) {
        int t = b * BT + (int)threadIdx.x;
        if (t == 0) mask[MASK_WORDS] = 0u;       // pad word (value unused)
        if (t <= NI) {
            int lo = 0, hi = NNZ_S;
            while (lo < hi) {
                int mid = (lo + hi) >> 1;
                if (s_rows[mid] < t) lo = mid + 1; else hi = mid;
            }
            s_rowptr[t] = lo;
        }
        int r = t - (NI + 1);
        if (r >= 0 && r <= NU) {
            int lo = 0, hi = NNZ_U;
            while (lo < hi) {
                int mid = (lo + hi) >> 1;
                if (u_rows[mid] < r) lo = mid + 1; else hi = mid;
            }
            u_rowptr[r] = lo;
        }
    } else {
        int t = (b - RP_BLOCKS) * BT + (int)threadIdx.x;
        if (t >= CV_TOTAL) return;
        float2 f = *(const float2*)(item_emb + (size_t)t * 2);
        xh[t] = __float22half2_rn(f);
    }
}

// ---------------------------------------------------------------------------
// 8-lane-group-per-row segmented SpMM on half x (VERBATIM R10) with
// software-pipelined cols/vals.
// ---------------------------------------------------------------------------
template <bool WRITE_H, bool WRITE_F>
__global__ void __launch_bounds__(256) spmm_h_kernel(
                            const int*   __restrict__ rowptr,
                            const int*   __restrict__ cols,
                            const float* __restrict__ vals,
                            const uint4* __restrict__ xh,
                            uint4*       __restrict__ yh,
                            float*       __restrict__ yf,
                            int n_rows) {
    int grp = (int)((blockIdx.x * blockDim.x + threadIdx.x) >> 3);  // row id
    int sub = threadIdx.x & 7;                                      // uint4 slot
    if (grp >= n_rows) return;

    int beg = rowptr[grp];
    int end = rowptr[grp + 1];

    float2 a0 = {0.f, 0.f}, a1 = {0.f, 0.f}, a2 = {0.f, 0.f}, a3 = {0.f, 0.f};

    // Preload first index batch
    int   c0 = 0, c1 = 0, c2 = 0, c3 = 0;
    float v0 = 0.f, v1 = 0.f, v2 = 0.f, v3 = 0.f;
    if (beg     < end) { c0 = __ldg(cols + beg);     v0 = __ldg(vals + beg);     }
    if (beg + 1 < end) { c1 = __ldg(cols + beg + 1); v1 = __ldg(vals + beg + 1); }
    if (beg + 2 < end) { c2 = __ldg(cols + beg + 2); v2 = __ldg(vals + beg + 2); }
    if (beg + 3 < end) { c3 = __ldg(cols + beg + 3); v3 = __ldg(vals + beg + 3); }

    for (int i = beg; i < end; i += 4) {
        // Prefetch next index batch (independent of current gathers)
        int n = i + 4;
        int   d0 = 0, d1 = 0, d2 = 0, d3 = 0;
        float w0 = 0.f, w1 = 0.f, w2 = 0.f, w3 = 0.f;
        if (n     < end) { d0 = __ldg(cols + n);     w0 = __ldg(vals + n);     }
        if (n + 1 < end) { d1 = __ldg(cols + n + 1); w1 = __ldg(vals + n + 1); }
        if (n + 2 < end) { d2 = __ldg(cols + n + 2); w2 = __ldg(vals + n + 2); }
        if (n + 3 < end) { d3 = __ldg(cols + n + 3); w3 = __ldg(vals + n + 3); }

        #define ACC_ONE(c, v)                                                  \
        {                                                                      \
            uint4 q = __ldg(xh + (size_t)(c) * 8 + sub);                       \
            float2 f0 = __half22float2(*(const __half2*)&q.x);                 \
            float2 f1 = __half22float2(*(const __half2*)&q.y);                 \
            float2 f2 = __half22float2(*(const __half2*)&q.z);                 \
            float2 f3 = __half22float2(*(const __half2*)&q.w);                 \
            a0.x = fmaf((v), f0.x, a0.x); a0.y = fmaf((v), f0.y, a0.y);        \
            a1.x = fmaf((v), f1.x, a1.x); a1.y = fmaf((v), f1.y, a1.y);        \
            a2.x = fmaf((v), f2.x, a2.x); a2.y = fmaf((v), f2.y, a2.y);        \
            a3.x = fmaf((v), f3.x, a3.x); a3.y = fmaf((v), f3.y, a3.y);        \
        }
        ACC_ONE(c0, v0)
        ACC_ONE(c1, v1)
        ACC_ONE(c2, v2)
        ACC_ONE(c3, v3)
        #undef ACC_ONE

        c0 = d0; c1 = d1; c2 = d2; c3 = d3;
        v0 = w0; v1 = w1; v2 = w2; v3 = w3;
    }

    if (WRITE_H) {
        __half2 h0 = __float22half2_rn(a0);
        __half2 h1 = __float22half2_rn(a1);
        __half2 h2 = __float22half2_rn(a2);
        __half2 h3 = __float22half2_rn(a3);
        uint4 q;
        q.x = *(const uint32_t*)&h0;
        q.y = *(const uint32_t*)&h1;
        q.z = *(const uint32_t*)&h2;
        q.w = *(const uint32_t*)&h3;
        yh[(size_t)grp * 8 + sub] = q;
    }
    if (WRITE_F) {
        float4 f0 = make_float4(a0.x, a0.y, a1.x, a1.y);
        float4 f1 = make_float4(a2.x, a2.y, a3.x, a3.y);
        *(float4*)(yf + (size_t)grp * NE + sub * 8)     = f0;
        *(float4*)(yf + (size_t)grp * NE + sub * 8 + 4) = f1;
    }
}

// ---------------------------------------------------------------------------
// U-spmm (VERBATIM R10): index-stream pipelining; dropout via bitmask with
// funnelshift. Kept edges accumulate unscaled; exact 1.25 scale at the end.
// ---------------------------------------------------------------------------
__global__ void __launch_bounds__(256) spmm_u_kernel(
                            const int*      __restrict__ rowptr,
                            const int*      __restrict__ cols,
                            const unsigned* __restrict__ mask,
                            const uint4*    __restrict__ xh,
                            float*          __restrict__ yf,
                            int n_rows) {
    int grp = (int)((blockIdx.x * blockDim.x + threadIdx.x) >> 3);  // row id
    int sub = threadIdx.x & 7;                                      // uint4 slot
    if (grp >= n_rows) return;

    int beg = rowptr[grp];
    int end = rowptr[grp + 1];

    float2 a0 = {0.f, 0.f}, a1 = {0.f, 0.f}, a2 = {0.f, 0.f}, a3 = {0.f, 0.f};

    #define LOAD_BATCH(base, BITS, C0, C1, C2, C3)                             \
    {                                                                          \
        if ((base) < end) {                                                    \
            unsigned w  = (unsigned)(base) >> 5;                               \
            unsigned sh = (unsigned)(base) & 31u;                              \
            unsigned m0 = __ldg(mask + w);                                     \
            unsigned m1 = __ldg(mask + w + 1);                                 \
            BITS = __funnelshift_r(m0, m1, sh);                                \
            int rem = end - (base); if (rem > 4) rem = 4;                      \
            BITS &= (1u << rem) - 1u;                                          \
            if (BITS & 1u) C0 = __ldg(cols + (base));                          \
            if (BITS & 2u) C1 = __ldg(cols + (base) + 1);                      \
            if (BITS & 4u) C2 = __ldg(cols + (base) + 2);                      \
            if (BITS & 8u) C3 = __ldg(cols + (base) + 3);                      \
        }                                                                      \
    }

    unsigned bits = 0u;
    int c0 = 0, c1 = 0, c2 = 0, c3 = 0;
    LOAD_BATCH(beg, bits, c0, c1, c2, c3)

    for (int i = beg; i < end; i += 4) {
        unsigned nbits = 0u;
        int d0 = 0, d1 = 0, d2 = 0, d3 = 0;
        LOAD_BATCH(i + 4, nbits, d0, d1, d2, d3)

        #define ACC_ONE(c, K)                                                  \
        if (bits & (K)) {                                                      \
            uint4 q = __ldg(xh + (size_t)(c) * 8 + sub);                       \
            float2 f0 = __half22float2(*(const __half2*)&q.x);                 \
            float2 f1 = __half22float2(*(const __half2*)&q.y);                 \
            float2 f2 = __half22float2(*(const __half2*)&q.z);                 \
            float2 f3 = __half22float2(*(const __half2*)&q.w);                 \
            a0.x += f0.x; a0.y += f0.y;                                        \
            a1.x += f1.x; a1.y += f1.y;                                        \
            a2.x += f2.x; a2.y += f2.y;                                        \
            a3.x += f3.x; a3.y += f3.y;                                        \
        }
        ACC_ONE(c0, 1u)
        ACC_ONE(c1, 2u)
        ACC_ONE(c2, 4u)
        ACC_ONE(c3, 8u)
        #undef ACC_ONE

        bits = nbits;
        c0 = d0; c1 = d1; c2 = d2; c3 = d3;
    }
    #undef LOAD_BATCH

    const float s = 1.25f;   // 1/keep, exact
    float4 f0 = make_float4(s * a0.x, s * a0.y, s * a1.x, s * a1.y);
    float4 f1 = make_float4(s * a2.x, s * a2.y, s * a3.x, s * a3.y);
    *(float4*)(yf + (size_t)grp * NE + sub * 8)     = f0;
    *(float4*)(yf + (size_t)grp * NE + sub * 8 + 4) = f1;
}

// ---------------------------------------------------------------------------
// Launch — capture-safe fork/join: mask generation (pure ALU) runs on a
// non-blocking side stream concurrently with the memory-latency-bound hops;
// joined via event before the U-spmm consumes the mask.
// ---------------------------------------------------------------------------
extern "C" void kernel_launch(void* const* d_in, const int* in_sizes, int n_in,
                              void* d_out, int out_size) {
    // Classify inputs by element count (robust to metadata ordering).
    const float* item_emb = nullptr;
    const void*  s_trip[3] = {nullptr, nullptr, nullptr};   // vals, rows, cols
    const void*  u_trip[3] = {nullptr, nullptr, nullptr};   // vals, rows, cols
    int si = 0, ui = 0;
    for (int k = 0; k < n_in; k++) {
        if (in_sizes[k] == NI * NE)      item_emb = (const float*)d_in[k];
        else if (in_sizes[k] == NNZ_S)   { if (si < 3) s_trip[si++] = d_in[k]; }
        else if (in_sizes[k] == NNZ_U)   { if (ui < 3) u_trip[ui++] = d_in[k]; }
    }
    const float* S_vals   = (const float*)s_trip[0];
    const int*   S_rows   = (const int*)  s_trip[1];
    const int*   S_cols   = (const int*)  s_trip[2];
    const int*   urm_rows = (const int*)  u_trip[1];
    const int*   urm_cols = (const int*)  u_trip[2];

    float* out_user = (float*)d_out;                       // [NU, NE]
    float* out_x    = (float*)d_out + (size_t)NU * NE;     // [NI, NE]

    // Resolve device-global scratch addresses (host side).
    uint4 *xh0, *xh1;
    unsigned *mask;
    int *s_rowptr, *u_rowptr;
    cudaGetSymbolAddress((void**)&xh0,      g_xh0);
    cudaGetSymbolAddress((void**)&xh1,      g_xh1);
    cudaGetSymbolAddress((void**)&mask,     g_mask);
    cudaGetSymbolAddress((void**)&s_rowptr, g_s_rowptr);
    cudaGetSymbolAddress((void**)&u_rowptr, g_u_rowptr);

    // Fork a non-blocking side stream off the (possibly captured) main stream.
    cudaStream_t s2 = nullptr;
    cudaEvent_t e1 = nullptr, e2 = nullptr;
    bool forked =
        cudaStreamCreateWithFlags(&s2, cudaStreamNonBlocking) == cudaSuccess &&
        cudaEventCreateWithFlags(&e1, cudaEventDisableTiming) == cudaSuccess &&
        cudaEventCreateWithFlags(&e2, cudaEventDisableTiming) == cudaSuccess;

    if (forked) {
        // Fork: side stream inherits the main stream's capture context.
        cudaEventRecord(e1, 0);
        cudaStreamWaitEvent(s2, e1, 0);
        // Dropout mask generation — ALU-only, overlaps the hops below.
        mask_kernel<<<UVM_BLOCKS, BT, 0, s2>>>(mask);
    }

    // Prologue: rowptrs + item_emb->half (+ mask pad word)
    prologue_kernel<<<RP_BLOCKS + CV_BLOCKS, BT>>>(
        mask, S_rows, urm_rows, s_rowptr, u_rowptr, item_emb, (__half2*)xh0);

    // 3-hop item-graph convolution (8-lane group per row: 32 rows / block)
    const int RPB = BT / 8;
    dim3 gridS((NI + RPB - 1) / RPB);
    spmm_h_kernel<true, false><<<gridS, BT>>>(
        s_rowptr, S_cols, S_vals, xh0, xh1, nullptr, NI);
    spmm_h_kernel<true, false><<<gridS, BT>>>(
        s_rowptr, S_cols, S_vals, xh1, xh0, nullptr, NI);
    spmm_h_kernel<true, true><<<gridS, BT>>>(
        s_rowptr, S_cols, S_vals, xh0, xh1, out_x, NI);

    if (forked) {
        // Join: U-spmm needs the completed mask.
        cudaEventRecord(e2, s2);
        cudaStreamWaitEvent(0, e2, 0);
    } else {
        // Fallback: serialize mask generation on the main stream.
        mask_kernel<<<UVM_BLOCKS, BT>>>(mask);
    }

    // user_emb = (dropout(URM)) @ x — bitmask dropout, half gathers
    dim3 gridU((NU + RPB - 1) / RPB);
    spmm_u_kernel<<<gridU, BT>>>(u_rowptr, urm_cols, mask, xh1, out_user, NU);

    // Host-side cleanup (safe: captured/enqueued work keeps its own refs).
    if (s2) cudaStreamDestroy(s2);
    if (e1) cudaEventDestroy(e1);
    if (e2) cudaEventDestroy(e2);
}